// round 6
// baseline (speedup 1.0000x reference)
#include <cuda_runtime.h>
#include <math.h>
#include <stdint.h>

#define SEQL 256
#define BATCH 64
#define HID 1024
#define GATES 4096
#define MROWS (SEQL*BATCH)      // 16384
#define BH (BATCH*HID)          // 65536

// ---------------- scratch (device globals; no cudaMalloc allowed) ----------
__device__ float g_xp[(size_t)MROWS * GATES];   // 256 MB: x-projection for one layer
__device__ float g_ys[(size_t)SEQL * BH];       // 64 MB: layer-0 h history
__device__ float g_hb[2 * BH];                  // layer-1 h ping-pong
__device__ volatile unsigned g_bar_gen;
__device__ unsigned g_bar_cnt;

// ---------------- helpers ---------------------------------------------------
__device__ __forceinline__ uint32_t f2tf32(float x) {
    uint32_t r; asm("cvt.rna.tf32.f32 %0, %1;" : "=r"(r) : "f"(x)); return r;
}
__device__ __forceinline__ void mma8(float* d, const uint32_t* a, const uint32_t* b) {
    asm volatile(
        "mma.sync.aligned.m16n8k8.row.col.f32.tf32.tf32.f32 "
        "{%0,%1,%2,%3},{%4,%5,%6,%7},{%8,%9},{%0,%1,%2,%3};"
        : "+f"(d[0]), "+f"(d[1]), "+f"(d[2]), "+f"(d[3])
        : "r"(a[0]), "r"(a[1]), "r"(a[2]), "r"(a[3]), "r"(b[0]), "r"(b[1]));
}
__device__ __forceinline__ void cpa16(uint32_t s, const void* g) {
    asm volatile("cp.async.cg.shared.global [%0], [%1], 16;" :: "r"(s), "l"(g));
}
#define CP_COMMIT() asm volatile("cp.async.commit_group;")
#define CP_WAIT(n)  asm volatile("cp.async.wait_group %0;" :: "n"(n))

__device__ __forceinline__ float sigf(float x) { return __fdividef(1.f, 1.f + __expf(-x)); }
__device__ __forceinline__ float tanhfast(float x) { return __fdividef(2.f, 1.f + __expf(-2.f * x)) - 1.f; }

// ---------------- grid barrier (all 128 blocks resident, 1/SM) --------------
__device__ __forceinline__ void gridbar(unsigned nblk) {
    __threadfence();
    __syncthreads();
    if (threadIdx.x == 0) {
        unsigned gen = g_bar_gen;
        if (atomicAdd(&g_bar_cnt, 1u) == nblk - 1u) {
            atomicExch(&g_bar_cnt, 0u);
            __threadfence();
            g_bar_gen = gen + 1u;
        } else {
            while (g_bar_gen == gen) { __nanosleep(32); }
            __threadfence();
        }
    }
    __syncthreads();
}

// ---------------- tf32 SGEMM: cp.async 2-stage pipelined (unchanged R3) -----
#define STG 8192   // floats per stage (As 4096 + Ws 4096)
__global__ __launch_bounds__(256, 2) void sgemm_xp(
    const float* __restrict__ A, const int* __restrict__ gidx,
    const float* __restrict__ W,
    const float* __restrict__ b1, const float* __restrict__ b2,
    float* __restrict__ C)
{
    extern __shared__ float smf[];
    const uint32_t smem_b = (uint32_t)__cvta_generic_to_shared(smf);
    const int bn = blockIdx.x * 128;
    const int bm = blockIdx.y * 128;
    const int tid = threadIdx.x;
    const int warp = tid >> 5, lane = tid & 31;
    const int g = lane >> 2, tig = lane & 3;
    const int wm = warp >> 2, wn = warp & 3;

    int cm[4]; int cj[4]; int arow[4]; uint32_t adst[4], wdst[4];
#pragma unroll
    for (int rep = 0; rep < 4; rep++) {
        int q = tid + rep * 256;
        int m = q >> 3, j = q & 7;
        cm[rep] = m; cj[rep] = j;
        arow[rep] = gidx ? gidx[bm + m] : (bm + m);
        uint32_t off = (uint32_t)(m * 32 + ((4 * j) ^ ((m & 7) << 2)));
        adst[rep] = smem_b + off * 4;
        wdst[rep] = smem_b + (off + 4096) * 4;
    }

    float acc[4][4][4];
#pragma unroll
    for (int mi = 0; mi < 4; mi++)
#pragma unroll
        for (int ni = 0; ni < 4; ni++)
#pragma unroll
            for (int r = 0; r < 4; r++) acc[mi][ni][r] = 0.f;

#pragma unroll
    for (int rep = 0; rep < 4; rep++) {
        cpa16(adst[rep], A + (size_t)arow[rep] * 1024 + 4 * cj[rep]);
        cpa16(wdst[rep], W + (size_t)(bn + cm[rep]) * 1024 + 4 * cj[rep]);
    }
    CP_COMMIT();

    const int swz = g << 2;
    for (int c = 0; c < 32; c++) {
        if (c + 1 < 32) {
            uint32_t so = (uint32_t)(((c + 1) & 1) * STG) * 4;
            int kc = (c + 1) * 32;
#pragma unroll
            for (int rep = 0; rep < 4; rep++) {
                cpa16(adst[rep] + so, A + (size_t)arow[rep] * 1024 + kc + 4 * cj[rep]);
                cpa16(wdst[rep] + so, W + (size_t)(bn + cm[rep]) * 1024 + kc + 4 * cj[rep]);
            }
        }
        CP_COMMIT();
        CP_WAIT(1);
        __syncthreads();

        const float* As = smf + (c & 1) * STG;
        const float* Ws = As + 4096;
#pragma unroll
        for (int kk = 0; kk < 4; kk++) {
            int kl = (kk * 8 + tig) ^ swz;
            int kh = (kk * 8 + tig + 4) ^ swz;
            uint32_t a[4][4], b[4][2];
#pragma unroll
            for (int mi = 0; mi < 4; mi++) {
                int base = (wm * 64 + mi * 16 + g) * 32;
                a[mi][0] = f2tf32(As[base + kl]);
                a[mi][1] = f2tf32(As[base + 256 + kl]);
                a[mi][2] = f2tf32(As[base + kh]);
                a[mi][3] = f2tf32(As[base + 256 + kh]);
            }
#pragma unroll
            for (int ni = 0; ni < 4; ni++) {
                int nb = (wn * 32 + ni * 8 + g) * 32;
                b[ni][0] = f2tf32(Ws[nb + kl]);
                b[ni][1] = f2tf32(Ws[nb + kh]);
            }
#pragma unroll
            for (int mi = 0; mi < 4; mi++)
#pragma unroll
                for (int ni = 0; ni < 4; ni++)
                    mma8(acc[mi][ni], a[mi], b[ni]);
        }
        __syncthreads();
    }

#pragma unroll
    for (int ni = 0; ni < 4; ni++) {
        int nc = bn + wn * 32 + ni * 8 + 2 * tig;
        float bia0 = b1[nc] + b2[nc];
        float bia1 = b1[nc + 1] + b2[nc + 1];
#pragma unroll
        for (int mi = 0; mi < 4; mi++) {
            int mr = bm + wm * 64 + mi * 16 + g;
            *(float2*)(C + (size_t)mr * GATES + nc) =
                make_float2(acc[mi][ni][0] + bia0, acc[mi][ni][1] + bia1);
            *(float2*)(C + (size_t)(mr + 8) * GATES + nc) =
                make_float2(acc[mi][ni][2] + bia0, acc[mi][ni][3] + bia1);
        }
    }
}
#define SGEMM_SMEM (2 * STG * 4)

// ---------------- persistent LSTM recurrence v2 ------------------------------
// 128 blocks x 256 threads (8 warps). Block owns 8 hidden cols (32 gate cols).
// warps 0-3: batch rows 16*wm..+15, k-half 0 of every staged chunk;
// warps 4-7: same rows, k-half 1. Cross-half reduce once per step via SMEM.
// ws2[k][j*4+gate] tf32, stride 40 -> one LDS.128 per 8-k window = b-frags
// for all 4 gates. c-state in registers.
#define PW2 40
#define PH 68
#define HS_OFF  (1024 * PW2)
#define RED_OFF (HS_OFF + 2 * 64 * PH)
#define REC_SMEM ((RED_OFF + 4 * 32 * 17) * 4)

__global__ __launch_bounds__(256, 1) void lstm_rec(
    const float* __restrict__ xp, const float* __restrict__ whh,
    float* hist, int mode, float* __restrict__ out_h, float* __restrict__ out_c)
{
    extern __shared__ float sm[];
    uint32_t* ws2 = (uint32_t*)sm;             // [1024][PW2] tf32
    float* hs  = sm + HS_OFF;                  // [2][64][PH]
    float* red = sm + RED_OFF;                 // [128][17]
    const uint32_t hs_u32 = (uint32_t)__cvta_generic_to_shared(hs);

    const int tid  = threadIdx.x;
    const int warp = tid >> 5, lane = tid & 31;
    const int g = lane >> 2, tig = lane & 3;
    const int wm = warp & 3;                   // batch group
    const int kh = warp >> 2;                  // k-half within chunk
    const int khb = kh * 32;
    const int j0 = blockIdx.x * 8;
    const int mrow = wm * 16 + g;              // batch rows: mrow, mrow+8

    // preload weights: ws2[k][c], c = j*4 + gate
    {
        int c  = tid & 31;                     // j = c>>2, gate = c&3
        int kq = tid >> 5;                     // 0..7, 128 k each
        int wrow = ((c & 3) << 10) + j0 + (c >> 2);
        const float4* w4 = (const float4*)(whh + (size_t)wrow * 1024);
        for (int k4 = kq * 32; k4 < kq * 32 + 32; k4++) {
            float4 v = w4[k4];
            int k = 4 * k4;
            ws2[(k+0)*PW2 + c] = f2tf32(v.x);
            ws2[(k+1)*PW2 + c] = f2tf32(v.y);
            ws2[(k+2)*PW2 + c] = f2tf32(v.z);
            ws2[(k+3)*PW2 + c] = f2tf32(v.w);
        }
    }
    __syncthreads();

    float cst[4] = {0.f, 0.f, 0.f, 0.f};   // c-state (kh==0 warps only)
    const int sb  = tid & 63;               // staging batch row
    const int skq = (tid >> 6) * 16;        // staging k quarter (16 k)

    for (int t = 0; t < SEQL; t++) {
        float2 xv[8];
        if (kh == 0) {
            const float* xpt = xp + (size_t)t * BATCH * GATES;
#pragma unroll
            for (int gi = 0; gi < 4; gi++)
#pragma unroll
                for (int ri = 0; ri < 2; ri++) {
                    int b = mrow + ri * 8;
                    xv[gi*2+ri] = *(const float2*)(xpt + (size_t)b * GATES + gi * 1024 + j0 + 2 * tig);
                }
        }

        float acc[4][4];
#pragma unroll
        for (int ni = 0; ni < 4; ni++)
#pragma unroll
            for (int r = 0; r < 4; r++) acc[ni][r] = 0.f;

        if (t > 0) {
            const float* hp = (mode == 0) ? hist + (size_t)(t-1) * BH
                                          : hist + (size_t)((t-1) & 1) * BH;
            // stage chunk 0
            {
                uint32_t s = hs_u32 + (sb * PH + skq) * 4;
                const float* gp = hp + (size_t)sb * 1024 + skq;
#pragma unroll
                for (int i = 0; i < 4; i++) cpa16(s + 16 * i, gp + 4 * i);
                CP_COMMIT();
            }
            for (int kc = 0; kc < 16; kc++) {
                if (kc < 15) {
                    int buf = (kc + 1) & 1;
                    uint32_t s = hs_u32 + (buf * 64 * PH + sb * PH + skq) * 4;
                    const float* gp = hp + (size_t)sb * 1024 + (kc + 1) * 64 + skq;
#pragma unroll
                    for (int i = 0; i < 4; i++) cpa16(s + 16 * i, gp + 4 * i);
                    CP_COMMIT();
                    CP_WAIT(1);
                } else {
                    CP_WAIT(0);
                }
                __syncthreads();
                const float* hb = hs + (kc & 1) * 64 * PH;
                const int kg = kc * 64;
#pragma unroll
                for (int kk = 0; kk < 4; kk++) {
                    int klo = khb + kk * 8 + tig;
                    uint32_t a[4];
                    a[0] = __float_as_uint(hb[mrow * PH + klo]);
                    a[1] = __float_as_uint(hb[(mrow + 8) * PH + klo]);
                    a[2] = __float_as_uint(hb[mrow * PH + klo + 4]);
                    a[3] = __float_as_uint(hb[(mrow + 8) * PH + klo + 4]);
                    uint4 blo = *(const uint4*)&ws2[(kg + klo) * PW2 + g * 4];
                    uint4 bhi = *(const uint4*)&ws2[(kg + klo + 4) * PW2 + g * 4];
                    const uint32_t* bl = (const uint32_t*)&blo;
                    const uint32_t* bh = (const uint32_t*)&bhi;
#pragma unroll
                    for (int ni = 0; ni < 4; ni++) {
                        uint32_t b2[2] = { bl[ni], bh[ni] };
                        mma8(acc[ni], a, b2);
                    }
                }
                __syncthreads();
            }
            // cross-half reduction: warps 4-7 -> smem, warps 0-3 accumulate
            if (kh == 1) {
                float* r = red + (wm * 32 + lane) * 17;
#pragma unroll
                for (int ni = 0; ni < 4; ni++)
#pragma unroll
                    for (int q = 0; q < 4; q++) r[ni * 4 + q] = acc[ni][q];
            }
            __syncthreads();
            if (kh == 0) {
                const float* r = red + (wm * 32 + lane) * 17;
#pragma unroll
                for (int ni = 0; ni < 4; ni++)
#pragma unroll
                    for (int q = 0; q < 4; q++) acc[ni][q] += r[ni * 4 + q];
            }
        }

        if (kh == 0) {
            float* hw = (mode == 0) ? hist + (size_t)t * BH
                                    : hist + (size_t)(t & 1) * BH;
#pragma unroll
            for (int ri = 0; ri < 2; ri++)
#pragma unroll
                for (int ci = 0; ci < 2; ci++) {
                    int r = ri * 2 + ci;
                    int b = mrow + ri * 8;
                    int jj = 2 * tig + ci;
                    float xi = ci ? xv[0*2+ri].y : xv[0*2+ri].x;
                    float xf = ci ? xv[1*2+ri].y : xv[1*2+ri].x;
                    float xg = ci ? xv[2*2+ri].y : xv[2*2+ri].x;
                    float xo = ci ? xv[3*2+ri].y : xv[3*2+ri].x;
                    float ii = sigf(acc[0][r] + xi);
                    float ff = sigf(acc[1][r] + xf);
                    float gg = tanhfast(acc[2][r] + xg);
                    float oo = sigf(acc[3][r] + xo);
                    float cn = ff * cst[r] + ii * gg;
                    float hn = oo * tanhfast(cn);
                    cst[r] = cn;
                    hw[(size_t)b * HID + j0 + jj] = hn;
                    if (t == SEQL - 1) {
                        out_h[(size_t)b * HID + j0 + jj] = hn;
                        out_c[(size_t)b * HID + j0 + jj] = cn;
                    }
                }
        }
        gridbar(gridDim.x);
    }
}

// ---------------- launch ----------------------------------------------------
extern "C" void kernel_launch(void* const* d_in, const int* in_sizes, int n_in,
                              void* d_out, int out_size)
{
    const int*   seq  = (const int*)d_in[0];
    const float* emb  = (const float*)d_in[1];
    const float* wih0 = (const float*)d_in[2];
    const float* whh0 = (const float*)d_in[3];
    const float* bih0 = (const float*)d_in[4];
    const float* bhh0 = (const float*)d_in[5];
    const float* wih1 = (const float*)d_in[6];
    const float* whh1 = (const float*)d_in[7];
    const float* bih1 = (const float*)d_in[8];
    const float* bhh1 = (const float*)d_in[9];
    float* out = (float*)d_out;

    float *xp, *ys, *hb;
    cudaGetSymbolAddress((void**)&xp, g_xp);
    cudaGetSymbolAddress((void**)&ys, g_ys);
    cudaGetSymbolAddress((void**)&hb, g_hb);

    cudaFuncSetAttribute(sgemm_xp, cudaFuncAttributeMaxDynamicSharedMemorySize, SGEMM_SMEM);
    cudaFuncSetAttribute(lstm_rec, cudaFuncAttributeMaxDynamicSharedMemorySize, REC_SMEM);

    dim3 gg(GATES / 128, MROWS / 128);   // (32, 128)

    // out layout: [h0 | h1 | c0 | c1], each 64x1024
    sgemm_xp<<<gg, 256, SGEMM_SMEM>>>(emb, seq, wih0, bih0, bhh0, xp);
    lstm_rec<<<128, 256, REC_SMEM>>>(xp, whh0, ys, 0, out, out + 2 * BH);

    sgemm_xp<<<gg, 256, SGEMM_SMEM>>>(ys, nullptr, wih1, bih1, bhh1, xp);
    lstm_rec<<<128, 256, REC_SMEM>>>(xp, whh1, hb, 1, out + BH, out + 3 * BH);
}

// round 7
// speedup vs baseline: 1.3359x; 1.3359x over previous
#include <cuda_runtime.h>
#include <math.h>
#include <stdint.h>

#define SEQL 256
#define BATCH 64
#define HID 1024
#define GATES 4096
#define MROWS (SEQL*BATCH)      // 16384
#define BH (BATCH*HID)          // 65536

// ---------------- scratch (device globals; no cudaMalloc allowed) ----------
__device__ float g_xp[(size_t)MROWS * GATES];   // 256 MB: x-projection for one layer
__device__ float g_ys[(size_t)SEQL * BH];       // 64 MB: layer-0 h history
__device__ float g_hb[2 * BH];                  // layer-1 h ping-pong
__device__ volatile unsigned g_bar_gen;
__device__ unsigned g_bar_cnt;

// ---------------- helpers ---------------------------------------------------
__device__ __forceinline__ uint32_t f2tf32(float x) {
    uint32_t r; asm("cvt.rna.tf32.f32 %0, %1;" : "=r"(r) : "f"(x)); return r;
}
__device__ __forceinline__ void mma8(float* d, const uint32_t* a, const uint32_t* b) {
    asm volatile(
        "mma.sync.aligned.m16n8k8.row.col.f32.tf32.tf32.f32 "
        "{%0,%1,%2,%3},{%4,%5,%6,%7},{%8,%9},{%0,%1,%2,%3};"
        : "+f"(d[0]), "+f"(d[1]), "+f"(d[2]), "+f"(d[3])
        : "r"(a[0]), "r"(a[1]), "r"(a[2]), "r"(a[3]), "r"(b[0]), "r"(b[1]));
}
__device__ __forceinline__ void cpa16(uint32_t s, const void* g) {
    asm volatile("cp.async.cg.shared.global [%0], [%1], 16;" :: "r"(s), "l"(g));
}
#define CP_COMMIT() asm volatile("cp.async.commit_group;")
#define CP_WAIT(n)  asm volatile("cp.async.wait_group %0;" :: "n"(n))

__device__ __forceinline__ float sigf(float x) { return __fdividef(1.f, 1.f + __expf(-x)); }
__device__ __forceinline__ float tanhfast(float x) { return __fdividef(2.f, 1.f + __expf(-2.f * x)) - 1.f; }

// ---------------- grid barrier (all 128 blocks resident, 1/SM) --------------
__device__ __forceinline__ void gridbar(unsigned nblk) {
    __threadfence();
    __syncthreads();
    if (threadIdx.x == 0) {
        unsigned gen = g_bar_gen;
        if (atomicAdd(&g_bar_cnt, 1u) == nblk - 1u) {
            atomicExch(&g_bar_cnt, 0u);
            __threadfence();
            g_bar_gen = gen + 1u;
        } else {
            while (g_bar_gen == gen) { __nanosleep(16); }
            __threadfence();
        }
    }
    __syncthreads();
}

// ---------------- tf32 SGEMM: cp.async 2-stage pipelined (unchanged R3) -----
#define STG 8192   // floats per stage (As 4096 + Ws 4096)
__global__ __launch_bounds__(256, 2) void sgemm_xp(
    const float* __restrict__ A, const int* __restrict__ gidx,
    const float* __restrict__ W,
    const float* __restrict__ b1, const float* __restrict__ b2,
    float* __restrict__ C)
{
    extern __shared__ float smf[];
    const uint32_t smem_b = (uint32_t)__cvta_generic_to_shared(smf);
    const int bn = blockIdx.x * 128;
    const int bm = blockIdx.y * 128;
    const int tid = threadIdx.x;
    const int warp = tid >> 5, lane = tid & 31;
    const int g = lane >> 2, tig = lane & 3;
    const int wm = warp >> 2, wn = warp & 3;

    int cm[4]; int cj[4]; int arow[4]; uint32_t adst[4], wdst[4];
#pragma unroll
    for (int rep = 0; rep < 4; rep++) {
        int q = tid + rep * 256;
        int m = q >> 3, j = q & 7;
        cm[rep] = m; cj[rep] = j;
        arow[rep] = gidx ? gidx[bm + m] : (bm + m);
        uint32_t off = (uint32_t)(m * 32 + ((4 * j) ^ ((m & 7) << 2)));
        adst[rep] = smem_b + off * 4;
        wdst[rep] = smem_b + (off + 4096) * 4;
    }

    float acc[4][4][4];
#pragma unroll
    for (int mi = 0; mi < 4; mi++)
#pragma unroll
        for (int ni = 0; ni < 4; ni++)
#pragma unroll
            for (int r = 0; r < 4; r++) acc[mi][ni][r] = 0.f;

#pragma unroll
    for (int rep = 0; rep < 4; rep++) {
        cpa16(adst[rep], A + (size_t)arow[rep] * 1024 + 4 * cj[rep]);
        cpa16(wdst[rep], W + (size_t)(bn + cm[rep]) * 1024 + 4 * cj[rep]);
    }
    CP_COMMIT();

    const int swz = g << 2;
    for (int c = 0; c < 32; c++) {
        if (c + 1 < 32) {
            uint32_t so = (uint32_t)(((c + 1) & 1) * STG) * 4;
            int kc = (c + 1) * 32;
#pragma unroll
            for (int rep = 0; rep < 4; rep++) {
                cpa16(adst[rep] + so, A + (size_t)arow[rep] * 1024 + kc + 4 * cj[rep]);
                cpa16(wdst[rep] + so, W + (size_t)(bn + cm[rep]) * 1024 + kc + 4 * cj[rep]);
            }
        }
        CP_COMMIT();
        CP_WAIT(1);
        __syncthreads();

        const float* As = smf + (c & 1) * STG;
        const float* Ws = As + 4096;
#pragma unroll
        for (int kk = 0; kk < 4; kk++) {
            int kl = (kk * 8 + tig) ^ swz;
            int kh = (kk * 8 + tig + 4) ^ swz;
            uint32_t a[4][4], b[4][2];
#pragma unroll
            for (int mi = 0; mi < 4; mi++) {
                int base = (wm * 64 + mi * 16 + g) * 32;
                a[mi][0] = f2tf32(As[base + kl]);
                a[mi][1] = f2tf32(As[base + 256 + kl]);
                a[mi][2] = f2tf32(As[base + kh]);
                a[mi][3] = f2tf32(As[base + 256 + kh]);
            }
#pragma unroll
            for (int ni = 0; ni < 4; ni++) {
                int nb = (wn * 32 + ni * 8 + g) * 32;
                b[ni][0] = f2tf32(Ws[nb + kl]);
                b[ni][1] = f2tf32(Ws[nb + kh]);
            }
#pragma unroll
            for (int mi = 0; mi < 4; mi++)
#pragma unroll
                for (int ni = 0; ni < 4; ni++)
                    mma8(acc[mi][ni], a[mi], b[ni]);
        }
        __syncthreads();
    }

#pragma unroll
    for (int ni = 0; ni < 4; ni++) {
        int nc = bn + wn * 32 + ni * 8 + 2 * tig;
        float bia0 = b1[nc] + b2[nc];
        float bia1 = b1[nc + 1] + b2[nc + 1];
#pragma unroll
        for (int mi = 0; mi < 4; mi++) {
            int mr = bm + wm * 64 + mi * 16 + g;
            *(float2*)(C + (size_t)mr * GATES + nc) =
                make_float2(acc[mi][ni][0] + bia0, acc[mi][ni][1] + bia1);
            *(float2*)(C + (size_t)(mr + 8) * GATES + nc) =
                make_float2(acc[mi][ni][2] + bia0, acc[mi][ni][3] + bia1);
        }
    }
}
#define SGEMM_SMEM (2 * STG * 4)

// ---------------- persistent LSTM recurrence v3 ------------------------------
// 128 blocks x 256 threads (8 warps). Block owns 8 hidden cols (32 gate cols).
// warp (wm = warp&3, kh = warp>>2): batch rows 16*wm..+15, k-half kh.
// Each warp runs a PRIVATE cp.async double-buffered pipeline over its 16
// chunks of 32 k — no block-wide sync in the k loop. Cross-half reduction via
// SMEM once per step (2 syncthreads), then grid barrier.
#define PW2 40
#define HPAD 36
#define CH_F (16 * HPAD)                        // 576 floats per chunk buffer
#define HS_OFF  (1024 * PW2)                    // float offset of warp buffers
#define RED_OFF (HS_OFF + 8 * 2 * CH_F)         // float offset of red buffer
#define REC_SMEM ((RED_OFF + 4 * 32 * 17) * 4)  // ~205 KB

__global__ __launch_bounds__(256, 1) void lstm_rec(
    const float* __restrict__ xp, const float* __restrict__ whh,
    float* hist, int mode, float* __restrict__ out_h, float* __restrict__ out_c)
{
    extern __shared__ float sm[];
    uint32_t* ws2 = (uint32_t*)sm;             // [1024][PW2] tf32
    float* red = sm + RED_OFF;                 // [128][17]

    const int tid  = threadIdx.x;
    const int warp = tid >> 5, lane = tid & 31;
    const int g = lane >> 2, tig = lane & 3;
    const int wm = warp & 3;                   // batch group
    const int kh = warp >> 2;                  // k-half (0: k<512, 1: k>=512)
    const int j0 = blockIdx.x * 8;
    const int mrow = wm * 16 + g;              // batch rows: mrow, mrow+8

    // warp-private double buffer (generic + shared-address forms)
    float* buf0 = sm + HS_OFF + warp * 2 * CH_F;
    float* buf1 = buf0 + CH_F;
    const uint32_t b0_u32 = (uint32_t)__cvta_generic_to_shared(buf0);
    const uint32_t b1_u32 = b0_u32 + CH_F * 4;

    // staging role: lane = r + 16*s covers row r, k_local [16s, 16s+16)
    const int sr = lane & 15;
    const int ss = lane >> 4;
    const uint32_t sdst0 = b0_u32 + (sr * HPAD + ss * 16) * 4;
    const uint32_t sdst1 = b1_u32 + (sr * HPAD + ss * 16) * 4;

    // preload weights: ws2[k][c], c = j*4 + gate
    {
        int c  = tid & 31;                     // j = c>>2, gate = c&3
        int kq = tid >> 5;                     // 0..7, 128 k each
        int wrow = ((c & 3) << 10) + j0 + (c >> 2);
        const float4* w4 = (const float4*)(whh + (size_t)wrow * 1024);
        for (int k4 = kq * 32; k4 < kq * 32 + 32; k4++) {
            float4 v = w4[k4];
            int k = 4 * k4;
            ws2[(k+0)*PW2 + c] = f2tf32(v.x);
            ws2[(k+1)*PW2 + c] = f2tf32(v.y);
            ws2[(k+2)*PW2 + c] = f2tf32(v.z);
            ws2[(k+3)*PW2 + c] = f2tf32(v.w);
        }
    }
    __syncthreads();

    float cst[4] = {0.f, 0.f, 0.f, 0.f};       // c-state (kh==0 warps only)
    const int khb = kh * 512;

    for (int t = 0; t < SEQL; t++) {
        float2 xv[8];
        if (kh == 0) {
            const float* xpt = xp + (size_t)t * BATCH * GATES;
#pragma unroll
            for (int gi = 0; gi < 4; gi++)
#pragma unroll
                for (int ri = 0; ri < 2; ri++) {
                    int b = mrow + ri * 8;
                    xv[gi*2+ri] = *(const float2*)(xpt + (size_t)b * GATES + gi * 1024 + j0 + 2 * tig);
                }
        }

        float acc[4][4];
#pragma unroll
        for (int ni = 0; ni < 4; ni++)
#pragma unroll
            for (int r = 0; r < 4; r++) acc[ni][r] = 0.f;

        if (t > 0) {
            const float* hp = (mode == 0) ? hist + (size_t)(t-1) * BH
                                          : hist + (size_t)((t-1) & 1) * BH;
            // lane's global source base for staging
            const float* src = hp + (size_t)(wm * 16 + sr) * 1024 + khb + ss * 16;

            // prologue: stage chunk 0 into buf0
#pragma unroll
            for (int i = 0; i < 4; i++) cpa16(sdst0 + 16 * i, src + 4 * i);
            CP_COMMIT();

            for (int kc = 0; kc < 16; kc++) {
                if (kc < 15) {
                    uint32_t d = ((kc + 1) & 1) ? sdst1 : sdst0;
                    const float* s = src + (kc + 1) * 32;
#pragma unroll
                    for (int i = 0; i < 4; i++) cpa16(d + 16 * i, s + 4 * i);
                    CP_COMMIT();
                    CP_WAIT(1);
                } else {
                    CP_WAIT(0);
                }
                __syncwarp();
                const float* hb = (kc & 1) ? buf1 : buf0;
                const int kg = khb + kc * 32;
#pragma unroll
                for (int kk = 0; kk < 4; kk++) {
                    int kloc = kk * 8 + tig;
                    uint32_t a[4];
                    a[0] = __float_as_uint(hb[g * HPAD + kloc]);
                    a[1] = __float_as_uint(hb[(g + 8) * HPAD + kloc]);
                    a[2] = __float_as_uint(hb[g * HPAD + kloc + 4]);
                    a[3] = __float_as_uint(hb[(g + 8) * HPAD + kloc + 4]);
                    uint4 blo = *(const uint4*)&ws2[(kg + kloc) * PW2 + g * 4];
                    uint4 bhi = *(const uint4*)&ws2[(kg + kloc + 4) * PW2 + g * 4];
                    const uint32_t* bl = (const uint32_t*)&blo;
                    const uint32_t* bh = (const uint32_t*)&bhi;
#pragma unroll
                    for (int ni = 0; ni < 4; ni++) {
                        uint32_t b2[2] = { bl[ni], bh[ni] };
                        mma8(acc[ni], a, b2);
                    }
                }
                __syncwarp();
            }
            // cross-half reduction: warps 4-7 -> smem, warps 0-3 accumulate
            if (kh == 1) {
                float* r = red + (wm * 32 + lane) * 17;
#pragma unroll
                for (int ni = 0; ni < 4; ni++)
#pragma unroll
                    for (int q = 0; q < 4; q++) r[ni * 4 + q] = acc[ni][q];
            }
            __syncthreads();
            if (kh == 0) {
                const float* r = red + (wm * 32 + lane) * 17;
#pragma unroll
                for (int ni = 0; ni < 4; ni++)
#pragma unroll
                    for (int q = 0; q < 4; q++) acc[ni][q] += r[ni * 4 + q];
            }
        }

        if (kh == 0) {
            float* hw = (mode == 0) ? hist + (size_t)t * BH
                                    : hist + (size_t)(t & 1) * BH;
#pragma unroll
            for (int ri = 0; ri < 2; ri++)
#pragma unroll
                for (int ci = 0; ci < 2; ci++) {
                    int r = ri * 2 + ci;
                    int b = mrow + ri * 8;
                    int jj = 2 * tig + ci;
                    float xi = ci ? xv[0*2+ri].y : xv[0*2+ri].x;
                    float xf = ci ? xv[1*2+ri].y : xv[1*2+ri].x;
                    float xg = ci ? xv[2*2+ri].y : xv[2*2+ri].x;
                    float xo = ci ? xv[3*2+ri].y : xv[3*2+ri].x;
                    float ii = sigf(acc[0][r] + xi);
                    float ff = sigf(acc[1][r] + xf);
                    float gg = tanhfast(acc[2][r] + xg);
                    float oo = sigf(acc[3][r] + xo);
                    float cn = ff * cst[r] + ii * gg;
                    float hn = oo * tanhfast(cn);
                    cst[r] = cn;
                    hw[(size_t)b * HID + j0 + jj] = hn;
                    if (t == SEQL - 1) {
                        out_h[(size_t)b * HID + j0 + jj] = hn;
                        out_c[(size_t)b * HID + j0 + jj] = cn;
                    }
                }
        }
        gridbar(gridDim.x);
    }
}

// ---------------- launch ----------------------------------------------------
extern "C" void kernel_launch(void* const* d_in, const int* in_sizes, int n_in,
                              void* d_out, int out_size)
{
    const int*   seq  = (const int*)d_in[0];
    const float* emb  = (const float*)d_in[1];
    const float* wih0 = (const float*)d_in[2];
    const float* whh0 = (const float*)d_in[3];
    const float* bih0 = (const float*)d_in[4];
    const float* bhh0 = (const float*)d_in[5];
    const float* wih1 = (const float*)d_in[6];
    const float* whh1 = (const float*)d_in[7];
    const float* bih1 = (const float*)d_in[8];
    const float* bhh1 = (const float*)d_in[9];
    float* out = (float*)d_out;

    float *xp, *ys, *hb;
    cudaGetSymbolAddress((void**)&xp, g_xp);
    cudaGetSymbolAddress((void**)&ys, g_ys);
    cudaGetSymbolAddress((void**)&hb, g_hb);

    cudaFuncSetAttribute(sgemm_xp, cudaFuncAttributeMaxDynamicSharedMemorySize, SGEMM_SMEM);
    cudaFuncSetAttribute(lstm_rec, cudaFuncAttributeMaxDynamicSharedMemorySize, REC_SMEM);

    dim3 gg(GATES / 128, MROWS / 128);   // (32, 128)

    // out layout: [h0 | h1 | c0 | c1], each 64x1024
    sgemm_xp<<<gg, 256, SGEMM_SMEM>>>(emb, seq, wih0, bih0, bhh0, xp);
    lstm_rec<<<128, 256, REC_SMEM>>>(xp, whh0, ys, 0, out, out + 2 * BH);

    sgemm_xp<<<gg, 256, SGEMM_SMEM>>>(ys, nullptr, wih1, bih1, bhh1, xp);
    lstm_rec<<<128, 256, REC_SMEM>>>(xp, whh1, hb, 1, out + BH, out + 3 * BH);
}